// round 17
// baseline (speedup 1.0000x reference)
#include <cuda_runtime.h>
#include <cuda_bf16.h>
#include <stdint.h>
#include <math.h>

#define NMAX 30000
#define EMAX 600000

// ---------------- scratch ----------------
__device__ float      d_xp  [NMAX * 256];
__device__ float      d_agg [NMAX * 256];
__device__ float      d_asrc[NMAX * 8];
__device__ float      d_adst[NMAX * 8];
__device__ ulonglong2 d_fcTp[64 * 256];    // fc_w^T packed: [k4][o] = 4 floats {w[4k4..4k4+3][o]}
__device__ ulonglong2 d_Wp  [8 * 32 * 32]; // W packed: [h][i4][d] = 4 floats {W[h][4i4..4i4+3][d]}
__device__ float      d_gsum;
__device__ float      d_xglob[256];
__device__ float      d_ga[256];
__device__ int        d_cnt[NMAX + 1];
__device__ int        d_cur[NMAX];
__device__ int        d_srcs[EMAX];
__device__ int        d_bsum[64];

// ---------------- helpers ----------------
__device__ __forceinline__ float lrelu(float x, float s) { return x > 0.f ? x : s * x; }

__device__ __forceinline__ float wredsum(float v) {
    #pragma unroll
    for (int s = 16; s; s >>= 1) v += __shfl_xor_sync(0xffffffffu, v, s);
    return v;
}
__device__ __forceinline__ float wredmax(float v) {
    #pragma unroll
    for (int s = 16; s; s >>= 1) v = fmaxf(v, __shfl_xor_sync(0xffffffffu, v, s));
    return v;
}

// packed f32x2 FMA: c = a*b + c
__device__ __forceinline__ void fma2(unsigned long long& c, unsigned long long a,
                                     unsigned long long b) {
    asm("fma.rn.f32x2 %0, %1, %2, %0;" : "+l"(c) : "l"(a), "l"(b));
}
__device__ __forceinline__ float unpack_sum(unsigned long long p) {
    float lo, hi;
    asm("mov.b64 {%0,%1}, %2;" : "=f"(lo), "=f"(hi) : "l"(p));
    return lo + hi;
}
__device__ __forceinline__ unsigned long long pack2(float lo, float hi) {
    unsigned long long r;
    asm("mov.b64 %0, {%1,%2};" : "=l"(r) : "f"(lo), "f"(hi));
    return r;
}
__device__ __forceinline__ void unpack2(unsigned long long p, float& lo, float& hi) {
    asm("mov.b64 {%0,%1}, %2;" : "=f"(lo), "=f"(hi) : "l"(p));
}

// block reduce of 16 per-thread values over 256 threads
__device__ __forceinline__ void reduce16(const float* v, float* sred, float* out,
                                         bool ismax, int tid) {
    int wid = tid >> 5, lane = tid & 31;
    #pragma unroll
    for (int m = 0; m < 16; m++) {
        float r = ismax ? wredmax(v[m]) : wredsum(v[m]);
        if (lane == 0) sred[m * 8 + wid] = r;
    }
    __syncthreads();
    if (tid < 16) {
        float r = sred[tid * 8];
        #pragma unroll
        for (int j = 1; j < 8; j++) {
            float t = sred[tid * 8 + j];
            r = ismax ? fmaxf(r, t) : r + t;
        }
        out[tid] = r;
    }
    __syncthreads();
}

// ---------------- fused setup: cnt zero + fc pack + W pack ----------------
__global__ void k_setup(const float* __restrict__ fc, const float* __restrict__ W, int n) {
    int idx = blockIdx.x * blockDim.x + threadIdx.x;  // 65536 threads
    {   // fc_w [o][k] -> packed [k4][o][4]
        int o = idx >> 8, k = idx & 255;
        ((float*)d_fcTp)[(k >> 2) * 1024 + o * 4 + (k & 3)] = fc[idx];
    }
    if (idx < 32768) {  // W [h][i][d] -> packed [h][i4][d][4]
        int h = idx >> 12, i = (idx >> 5) & 127, d = idx & 31;
        ((float*)d_Wp)[(((h * 32) + (i >> 2)) * 32 + d) * 4 + (i & 3)] = W[idx];
    }
    if (idx <= n) d_cnt[idx] = 0;
    if (idx < 256) d_xglob[idx] = 0.f;
    if (idx == 0) d_gsum = 0.f;
}

// ---------------- CSR build (proven) ----------------
__global__ void k_hist(const int* __restrict__ ei, int E) {
    int e = blockIdx.x * blockDim.x + threadIdx.x;
    if (e < E) atomicAdd(&d_cnt[ei[E + e]], 1);
}
__global__ void k_scan1(int n) {
    __shared__ int sh[1024];
    int b = blockIdx.x, t = threadIdx.x;
    int i = b * 1024 + t;
    int v = (i < n) ? d_cnt[i] : 0;
    sh[t] = v;
    __syncthreads();
    #pragma unroll
    for (int off = 1; off < 1024; off <<= 1) {
        int x = (t >= off) ? sh[t - off] : 0;
        __syncthreads();
        sh[t] += x;
        __syncthreads();
    }
    if (i < n) d_cur[i] = sh[t] - v;
    if (t == 1023) d_bsum[b] = sh[1023];
}
__global__ void k_scan2(int nb) {
    int t = threadIdx.x;
    int v = (t < nb) ? d_bsum[t] : 0;
    int orig = v;
    #pragma unroll
    for (int off = 1; off < 32; off <<= 1) {
        int x = __shfl_up_sync(0xffffffffu, v, off);
        if (t >= off) v += x;
    }
    if (t < nb) d_bsum[t] = v - orig;
}
__global__ void k_scan3(int n, int E) {
    int b = blockIdx.x, t = threadIdx.x;
    int i = b * 1024 + t;
    if (i < n) {
        int v = d_cur[i] + d_bsum[b];
        d_cnt[i] = v;
        d_cur[i] = v;
    }
    if (i == 0) d_cnt[n] = E;
}
__global__ void k_scatter(const int* __restrict__ ei, int E) {
    int e = blockIdx.x * blockDim.x + threadIdx.x;
    if (e >= E) return;
    int d = ei[E + e];
    int pos = atomicAdd(&d_cur[d], 1);
    d_srcs[pos] = ei[e];
}

// ---------------- xp + alpha (f32x2 inner loop, proven) ----------------
__global__ void __launch_bounds__(256)
k_xp(const float* __restrict__ x,
     const float* __restrict__ a_src, const float* __restrict__ a_dst, int n) {
    __shared__ __align__(16) float xs[8][128];
    int tid = threadIdx.x;
    int n0 = blockIdx.x * 8;
    for (int idx = tid; idx < 8 * 128; idx += 256) {
        int m = idx >> 7, i = idx & 127;
        int nn = n0 + m;
        xs[m][i] = (nn < n) ? x[(size_t)nn * 128 + i] : 0.f;
    }
    __syncthreads();

    int h = tid >> 5, d = tid & 31;
    unsigned long long acc2[8];
    #pragma unroll
    for (int m = 0; m < 8; m++) acc2[m] = 0ull;
    const ulonglong2* Wp = d_Wp + (size_t)h * 32 * 32 + d;
    #pragma unroll 1
    for (int i4 = 0; i4 < 32; i4++) {
        ulonglong2 wv = Wp[i4 * 32];
        #pragma unroll
        for (int m = 0; m < 8; m++) {
            ulonglong2 xv = ((const ulonglong2*)xs[m])[i4];
            fma2(acc2[m], xv.x, wv.x);
            fma2(acc2[m], xv.y, wv.y);
        }
    }

    float asv = a_src[h * 32 + d];
    float adv = a_dst[h * 32 + d];
    int lane = tid & 31;
    #pragma unroll
    for (int m = 0; m < 8; m++) {
        float acc = unpack_sum(acc2[m]);
        int nn = n0 + m;
        float rs = wredsum(acc * asv);
        float rd = wredsum(acc * adv);
        if (nn < n) {
            d_xp[(size_t)nn * 256 + tid] = acc;
            if (lane == 0) {
                d_asrc[nn * 8 + h] = rs;
                d_adst[nn * 8 + h] = rd;
            }
        }
    }
}

// ---------------- fused attention aggregation (+conv_b) ----------------
// 2 warps per dst node: warp parity c owns row floats [c*128, c*128+128).
// Each lane: 1 LDG.128 per edge + 2 FFMA2. Both warps redundantly compute the
// 8 attention scalars in lanes 0-7 (asrc/adst tiny, L2-hot).
// head of lane L's 16B chunk = c*4 + (L>>3); fma2 pairs never straddle heads.
__global__ void __launch_bounds__(256)
k_agg(const float* __restrict__ conv_b, int n) {
    int w = threadIdx.x >> 5;
    int lane = threadIdx.x & 31;
    int d = blockIdx.x * 4 + (w >> 1);
    int c = w & 1;
    if (d >= n) return;
    int beg = d_cnt[d], end = d_cnt[d + 1];
    float adstv = (lane < 8) ? d_adst[d * 8 + lane] : 0.f;
    float esum = 0.f;
    unsigned long long acc2[2] = {0ull, 0ull};
    int hsel = c * 4 + (lane >> 3);

    // pipeline: self loop first, prefetch next
    int s_cur = d;
    ulonglong2 r = ((const ulonglong2*)(d_xp + (size_t)s_cur * 256))[c * 32 + lane];
    float as_cur = (lane < 8) ? d_asrc[s_cur * 8 + lane] : 0.f;
    int p = beg;

    while (true) {
        int s_nxt = (p < end) ? d_srcs[p] : -1;
        ulonglong2 rn;
        float as_nxt = 0.f;
        if (s_nxt >= 0) {
            rn = ((const ulonglong2*)(d_xp + (size_t)s_nxt * 256))[c * 32 + lane];
            if (lane < 8) as_nxt = d_asrc[s_nxt * 8 + lane];
        }
        float av = 0.f;
        if (lane < 8) {
            av = __expf(lrelu(as_cur + adstv, 0.2f));
            esum += av;
        }
        float ah = __shfl_sync(0xffffffffu, av, hsel);
        unsigned long long a = pack2(ah, ah);
        fma2(acc2[0], r.x, a);
        fma2(acc2[1], r.y, a);
        if (s_nxt < 0) break;
        r = rn;
        as_cur = as_nxt;
        p++;
    }

    float sh = __shfl_sync(0xffffffffu, esum, hsel);
    float inv = 1.f / (sh + 1e-16f);
    float4 cb = ((const float4*)conv_b)[c * 32 + lane];
    float lo, hi;
    float4 o;
    unpack2(acc2[0], lo, hi); o.x = lo * inv + cb.x; o.y = hi * inv + cb.y;
    unpack2(acc2[1], lo, hi); o.z = lo * inv + cb.z; o.w = hi * inv + cb.w;
    ((float4*)(d_agg + (size_t)d * 256))[c * 32 + lane] = o;
}

// ---------------- dense per-node chain (f32x2) + fused global pooling (proven) ----------------
__global__ void __launch_bounds__(256)
k_dense(const float* __restrict__ fc_b,
        const float* __restrict__ ln_w, const float* __restrict__ ln_b,
        const float* __restrict__ gw, const float* __restrict__ gb, int n) {
    __shared__ __align__(16) float vs[16][256];
    __shared__ float sred[16 * 8];
    __shared__ float sbc[16];
    __shared__ float sbc2[16];
    int tid = threadIdx.x;
    int n0 = blockIdx.x * 16;
    float fb = fc_b[tid];
    float lw = ln_w[tid], lb = ln_b[tid];

    #pragma unroll
    for (int m = 0; m < 16; m++) {
        int nn = n0 + m;
        vs[m][tid] = (nn < n) ? d_agg[(size_t)nn * 256 + tid] : 0.f;
    }
    __syncthreads();

    unsigned long long c2[16];
    #pragma unroll
    for (int m = 0; m < 16; m++) c2[m] = 0ull;
    #pragma unroll 1
    for (int k4 = 0; k4 < 64; k4++) {
        ulonglong2 w = d_fcTp[k4 * 256 + tid];
        #pragma unroll
        for (int m = 0; m < 16; m++) {
            ulonglong2 a = ((const ulonglong2*)vs[m])[k4];
            fma2(c2[m], a.x, w.x);
            fma2(c2[m], a.y, w.y);
        }
    }
    float acc[16];
    #pragma unroll
    for (int m = 0; m < 16; m++) acc[m] = lrelu(unpack_sum(c2[m]) + fb, 0.01f);

    reduce16(acc, sred, sbc, true, tid);
    float e[16];
    #pragma unroll
    for (int m = 0; m < 16; m++) e[m] = __expf(acc[m] - sbc[m]);
    reduce16(e, sred, sbc2, false, tid);

    float x2[16];
    #pragma unroll
    for (int m = 0; m < 16; m++) {
        float sa = e[m] / sbc2[m];
        x2[m] = lrelu(vs[m][tid] * sa, 0.2f);
    }
    __syncthreads();
    #pragma unroll
    for (int m = 0; m < 16; m++) vs[m][tid] = x2[m];
    __syncthreads();

    #pragma unroll
    for (int m = 0; m < 16; m++) c2[m] = 0ull;
    #pragma unroll 1
    for (int k4 = 0; k4 < 64; k4++) {
        ulonglong2 w = d_fcTp[k4 * 256 + tid];
        #pragma unroll
        for (int m = 0; m < 16; m++) {
            ulonglong2 a = ((const ulonglong2*)vs[m])[k4];
            fma2(c2[m], a.x, w.x);
            fma2(c2[m], a.y, w.y);
        }
    }
    #pragma unroll
    for (int m = 0; m < 16; m++) acc[m] = unpack_sum(c2[m]) + fb;

    reduce16(acc, sred, sbc, false, tid);
    float mu[16], sq[16];
    #pragma unroll
    for (int m = 0; m < 16; m++) {
        mu[m] = sbc[m] * (1.f / 256.f);
        float dd = acc[m] - mu[m];
        sq[m] = dd * dd;
    }
    reduce16(sq, sred, sbc2, false, tid);
    float xl[16];
    #pragma unroll
    for (int m = 0; m < 16; m++) {
        float var = sbc2[m] * (1.f / 256.f);
        xl[m] = (acc[m] - mu[m]) * rsqrtf(var + 1e-5f) * lw + lb;
    }

    #pragma unroll
    for (int m = 0; m < 16; m++) sq[m] = xl[m] * xl[m];
    reduce16(sq, sred, sbc, false, tid);
    #pragma unroll
    for (int m = 0; m < 16; m++) xl[m] /= fmaxf(sqrtf(sbc[m]), 1e-12f);

    float gwt = gw[tid];
    #pragma unroll
    for (int m = 0; m < 16; m++) sq[m] = xl[m] * gwt;
    reduce16(sq, sred, sbc2, false, tid);

    float gb0 = gb[0];
    float pool = 0.f;
    float evsum = 0.f;
    #pragma unroll
    for (int m = 0; m < 16; m++) {
        if (n0 + m < n) {
            d_agg[(size_t)(n0 + m) * 256 + tid] = xl[m];
            float ev = __expf(sbc2[m] + gb0);
            pool += ev * xl[m];
            evsum += ev;
        }
    }
    atomicAdd(&d_xglob[tid], pool);
    if (tid == 0) atomicAdd(&d_gsum, evsum);
}

// ---------------- final ga + output ----------------
__global__ void k_ga(const float* __restrict__ gfcw, const float* __restrict__ gfcb) {
    __shared__ float xg[256];
    __shared__ float r8[8];
    __shared__ float bres;
    int tid = threadIdx.x;
    xg[tid] = d_xglob[tid] / (d_gsum + 1e-16f);
    __syncthreads();
    float acc = gfcb[tid];
    const float* row = gfcw + (size_t)tid * 256;
    #pragma unroll 4
    for (int k = 0; k < 256; k++) acc += xg[k] * row[k];
    acc = fmaxf(acc, 0.f);
    float r = wredmax(acc);
    if ((tid & 31) == 0) r8[tid >> 5] = r;
    __syncthreads();
    if (tid == 0) {
        float m = r8[0];
        #pragma unroll
        for (int j = 1; j < 8; j++) m = fmaxf(m, r8[j]);
        bres = m;
    }
    __syncthreads();
    float e = __expf(acc - bres);
    r = wredsum(e);
    if ((tid & 31) == 0) r8[tid >> 5] = r;
    __syncthreads();
    if (tid == 0) {
        float s = 0.f;
        #pragma unroll
        for (int j = 0; j < 8; j++) s += r8[j];
        bres = s;
    }
    __syncthreads();
    d_ga[tid] = e / bres;
}

__global__ void k_out(float* __restrict__ out, int n) {
    int idx = blockIdx.x * blockDim.x + threadIdx.x;
    if (idx >= n * 64) return;
    int o4 = idx & 63;
    float4 g = ((const float4*)d_ga)[o4];
    float4 v = ((const float4*)d_agg)[idx];
    v.x *= g.x; v.y *= g.y; v.z *= g.z; v.w *= g.w;
    ((float4*)out)[idx] = v;
}

// ---------------- launch ----------------
extern "C" void kernel_launch(void* const* d_in, const int* in_sizes, int n_in,
                              void* d_out, int out_size) {
    const float* x      = (const float*)d_in[0];
    const int*   ei     = (const int*)  d_in[1];
    const float* W      = (const float*)d_in[4];
    const float* a_src  = (const float*)d_in[5];
    const float* a_dst  = (const float*)d_in[6];
    const float* conv_b = (const float*)d_in[7];
    const float* fc_w   = (const float*)d_in[8];
    const float* fc_b   = (const float*)d_in[9];
    const float* ln_w   = (const float*)d_in[10];
    const float* ln_b   = (const float*)d_in[11];
    const float* gate_w = (const float*)d_in[12];
    const float* gate_b = (const float*)d_in[13];
    const float* gfc_w  = (const float*)d_in[14];
    const float* gfc_b  = (const float*)d_in[15];
    float* out = (float*)d_out;

    int n = in_sizes[0] / 128;
    int E = in_sizes[1] / 2;
    int nb = (n + 1023) / 1024;

    k_setup<<<256, 256>>>(fc_w, W, n);
    k_hist<<<(E + 255) / 256, 256>>>(ei, E);
    k_scan1<<<nb, 1024>>>(n);
    k_scan2<<<1, 32>>>(nb);
    k_scan3<<<nb, 1024>>>(n, E);
    k_scatter<<<(E + 255) / 256, 256>>>(ei, E);
    k_xp<<<(n + 7) / 8, 256>>>(x, a_src, a_dst, n);
    k_agg<<<(n + 3) / 4, 256>>>(conv_b, n);
    k_dense<<<(n + 15) / 16, 256>>>(fc_b, ln_w, ln_b, gate_w, gate_b, n);
    k_ga<<<1, 256>>>(gfc_w, gfc_b);
    k_out<<<(n * 64 + 255) / 256, 256>>>(out, n);
}